// round 17
// baseline (speedup 1.0000x reference)
#include <cuda_runtime.h>
#include <cuda_fp16.h>
#include <cstdint>
#include <math.h>

// Problem constants
#define T_    128
#define B_    64
#define TB_   8192      // T*B
#define N_    24        // joints
#define D_    256
#define H_    8
#define F_    32
#define HF_   256       // H*F
#define ND_   6144      // N*D
#define OUTW_ 6144      // N*H*F
#define M1_   196608    // TB*N rows for KV gemm

// fp16 scratch
__device__ __half g_q[TB_ * H_ * N_ * F_];
__device__ __half g_k[TB_ * H_ * N_ * F_];
__device__ __half g_v[TB_ * H_ * N_ * F_];
// fp16 copies of inputs (pre-converted once)
__device__ __half g_xh[TB_ * ND_];            // X   (100 MB)
__device__ __half g_wkh[HF_ * D_];
__device__ __half g_wvh[HF_ * D_];
__device__ __half g_wqh[H_ * N_ * F_ * D_];

// ---------------------------------------------------------------------------
// helpers
// ---------------------------------------------------------------------------
__device__ __forceinline__ uint32_t smem_u32(const void* p) {
    uint32_t a;
    asm("{ .reg .u64 t; cvta.to.shared.u64 t, %1; cvt.u32.u64 %0, t; }"
        : "=r"(a) : "l"(p));
    return a;
}
__device__ __forceinline__ void cp_async16(uint32_t dst, const void* src) {
    asm volatile("cp.async.cg.shared.global [%0], [%1], 16;"
                 :: "r"(dst), "l"(src) : "memory");
}
__device__ __forceinline__ void cp_commit() {
    asm volatile("cp.async.commit_group;" ::: "memory");
}
__device__ __forceinline__ void cp_wait1() {
    asm volatile("cp.async.wait_group 1;" ::: "memory");
}
__device__ __forceinline__ void cp_wait0() {
    asm volatile("cp.async.wait_group 0;" ::: "memory");
}
// fp16 m16n8k16, fp32 accumulate
__device__ __forceinline__ void mma_f16(float c[4], const uint32_t a[4],
                                        const uint32_t b[2]) {
    asm volatile(
        "mma.sync.aligned.m16n8k16.row.col.f32.f16.f16.f32 "
        "{%0,%1,%2,%3}, {%4,%5,%6,%7}, {%8,%9}, {%0,%1,%2,%3};"
        : "+f"(c[0]), "+f"(c[1]), "+f"(c[2]), "+f"(c[3])
        : "r"(a[0]), "r"(a[1]), "r"(a[2]), "r"(a[3]), "r"(b[0]), "r"(b[1]));
}
__device__ __forceinline__ uint32_t packh2(float x, float y) {
    __half2 h = __floats2half2_rn(x, y);
    return *reinterpret_cast<uint32_t*>(&h);
}
// warp-cooperative fragment load: 4 x (8x8 b16) matrices
#define LDMX4(d0, d1, d2, d3, addr)                                         \
    asm volatile("ldmatrix.sync.aligned.m8n8.x4.shared.b16 "                \
                 "{%0,%1,%2,%3}, [%4];"                                     \
                 : "=r"(d0), "=r"(d1), "=r"(d2), "=r"(d3) : "r"(addr))

// Smem geometry: K-chunk 64 halves = 32 words/row, padded to 36 words (144B).
// ldmatrix bank check: 8 consecutive rows at 36-word stride hit word offsets
// {0,4,...,28} mod 32 -> each 8-address phase covers all 32 banks once.
#define ROWW     36                         // words per row
#define ROWB     144                        // bytes per row
#define TILE_BYTES (128 * ROWW * 4)         // 18432

// KV fused: stage = A + Bk + Bv
#define KV_STAGE   (3 * TILE_BYTES)         // 55296
#define KV_NSTG    3
#define KV_SMEM    (KV_NSTG * KV_STAGE + 1024)  // 166912 -> 1 CTA/SM

// Q: stage = A + B
#define Q_STAGE    (2 * TILE_BYTES)         // 36864
#define Q_NSTG     3
#define Q_SMEM     (Q_NSTG * Q_STAGE + 1024)    // 111616 -> 2 CTA/SM

// ---------------------------------------------------------------------------
// Pre-pass: fp32 -> fp16, vectorized.
// ---------------------------------------------------------------------------
__global__ void conv_h_kernel(const float4* __restrict__ src,
                              uint2* __restrict__ dst, int n4)
{
    for (int i = blockIdx.x * blockDim.x + threadIdx.x; i < n4;
         i += gridDim.x * blockDim.x) {
        float4 v = src[i];
        __half2 a = __floats2half2_rn(v.x, v.y);
        __half2 b = __floats2half2_rn(v.z, v.w);
        uint2 u;
        u.x = *reinterpret_cast<const uint32_t*>(&a);
        u.y = *reinterpret_cast<const uint32_t*>(&b);
        dst[i] = u;
    }
}

// Per-lane ldmatrix source offsets (bytes), relative to tile base:
//  A (x4 = a0,a1,a2,a3): m0 rows0-7 k0 | m1 rows8-15 k0 | m2 rows0-7 k8 | m3 rows8-15 k8
//  B (x4 = b0(ni),b1(ni),b0(ni+1),b1(ni+1)):
//     m0 rows0-7 k0 | m1 rows0-7 k8 | m2 rows8-15 k0 | m3 rows8-15 k8
#define A_LANE_OFF(mBase, lane) \
    ((uint32_t)(((mBase) + (((lane) >> 3) & 1) * 8 + ((lane) & 7)) * ROWB + (((lane) >> 4) & 1) * 16))
#define B_LANE_OFF(nBase, lane) \
    ((uint32_t)(((nBase) + (((lane) >> 4) & 1) * 8 + ((lane) & 7)) * ROWB + (((lane) >> 3) & 1) * 16))

// ---------------------------------------------------------------------------
// Kernel 1: fused K+V projection. grid (2, 1536): x=N-tile, y=M-tile.
// ---------------------------------------------------------------------------
__global__ void __launch_bounds__(256, 1)
kv_mma_kernel(const float* __restrict__ bk, const float* __restrict__ bv)
{
    extern __shared__ char smem[];
    const int tid  = threadIdx.x;
    const int w    = tid >> 5, lane = tid & 31;
    const int gid  = lane >> 2, tig = lane & 3;
    const int mWarp = (w & 1) * 64;
    const int nWarp = (w >> 1) * 32;
    const int colBase = blockIdx.x * 128;
    const int rowBase = blockIdx.y * 128;
    const uint32_t sb = smem_u32(smem);

    const uint32_t aLane = A_LANE_OFF(mWarp, lane);
    const uint32_t bLane = B_LANE_OFF(nWarp, lane);

    float* sbK = (float*)(smem + KV_NSTG * KV_STAGE);
    float* sbV = sbK + 128;
    if (tid < 128) { sbK[tid] = bk[colBase + tid]; sbV[tid] = bv[colBase + tid]; }

    float cK[4][4][4], cV[4][4][4];
#pragma unroll
    for (int mi = 0; mi < 4; mi++)
#pragma unroll
        for (int ni = 0; ni < 4; ni++)
#pragma unroll
            for (int j = 0; j < 4; j++) { cK[mi][ni][j] = 0.f; cV[mi][ni][j] = 0.f; }

    auto load_stage = [&](int ch) {
        const int s = ch % KV_NSTG;
        const int k0 = ch * 64;                 // halves
        const uint32_t aBase  = sb + s * KV_STAGE;
        const uint32_t bkBase = aBase + TILE_BYTES;
        const uint32_t bvBase = aBase + 2 * TILE_BYTES;
#pragma unroll
        for (int j = 0; j < 4; j++) {
            const int e = tid + 256 * j;
            const int r = e >> 3, cc = e & 7;   // 8 x 16B per 128B row
            const uint32_t soff = (uint32_t)(r * ROWB + cc * 16);
            cp_async16(aBase + soff,
                       g_xh + (size_t)(rowBase + r) * D_ + k0 + cc * 8);
            cp_async16(bkBase + soff,
                       g_wkh + (size_t)(colBase + r) * D_ + k0 + cc * 8);
            cp_async16(bvBase + soff,
                       g_wvh + (size_t)(colBase + r) * D_ + k0 + cc * 8);
        }
    };

    load_stage(0); cp_commit();
    load_stage(1); cp_commit();

    for (int ch = 0; ch < 4; ch++) {
        if (ch < 3) cp_wait1(); else cp_wait0();
        __syncthreads();
        if (ch + 2 < 4) { load_stage(ch + 2); cp_commit(); }
        const uint32_t aBase  = sb + (ch % KV_NSTG) * KV_STAGE;
        const uint32_t bkBase = aBase + TILE_BYTES;
        const uint32_t bvBase = aBase + 2 * TILE_BYTES;
#pragma unroll
        for (int ks = 0; ks < 4; ks++) {
            const uint32_t kOff = (uint32_t)(ks * 32);      // 8 words = 32 B
            uint32_t af[4][4];
#pragma unroll
            for (int mi = 0; mi < 4; mi++)
                LDMX4(af[mi][0], af[mi][1], af[mi][2], af[mi][3],
                      aBase + aLane + (uint32_t)(mi * 16 * ROWB) + kOff);
            uint32_t bK[4][2], bV[4][2];
#pragma unroll
            for (int np = 0; np < 2; np++) {                // ni pairs (0,1),(2,3)
                const uint32_t bo = bLane + (uint32_t)(np * 16 * ROWB) + kOff;
                LDMX4(bK[2 * np][0], bK[2 * np][1], bK[2 * np + 1][0], bK[2 * np + 1][1],
                      bkBase + bo);
                LDMX4(bV[2 * np][0], bV[2 * np][1], bV[2 * np + 1][0], bV[2 * np + 1][1],
                      bvBase + bo);
            }
#pragma unroll
            for (int ni = 0; ni < 4; ni++)
#pragma unroll
                for (int mi = 0; mi < 4; mi++) {
                    mma_f16(cK[mi][ni], af[mi], bK[ni]);
                    mma_f16(cV[mi][ni], af[mi], bV[ni]);
                }
        }
    }

#pragma unroll
    for (int mi = 0; mi < 4; mi++) {
        const int r0 = rowBase + mWarp + mi * 16 + gid;
#pragma unroll
        for (int rr = 0; rr < 2; rr++) {
            const int m = r0 + rr * 8;
            const int tb = m / N_, n = m - tb * N_;
#pragma unroll
            for (int ni = 0; ni < 4; ni++) {
                const int oc = nWarp + ni * 8 + tig * 2;
                const int o = colBase + oc;
                const int h = o >> 5, f = o & 31;
                const size_t idx = (((size_t)tb * H_ + h) * N_ + n) * F_ + f;
                __half2 vk = __floats2half2_rn(cK[mi][ni][2 * rr + 0] + sbK[oc],
                                               cK[mi][ni][2 * rr + 1] + sbK[oc + 1]);
                __half2 vv = __floats2half2_rn(cV[mi][ni][2 * rr + 0] + sbV[oc],
                                               cV[mi][ni][2 * rr + 1] + sbV[oc + 1]);
                *(__half2*)&g_k[idx] = vk;
                *(__half2*)&g_v[idx] = vv;
            }
        }
    }
}

// ---------------------------------------------------------------------------
// Kernel 2: Q projection. grid (2, 24, 64): x=N-tile, y=joint, z=tb-tile.
// ---------------------------------------------------------------------------
__global__ void __launch_bounds__(256, 2)
q_mma_kernel(const float* __restrict__ bq)
{
    extern __shared__ char smem[];
    const int nJ = blockIdx.y;

    const int tid  = threadIdx.x;
    const int w    = tid >> 5, lane = tid & 31;
    const int gid  = lane >> 2, tig = lane & 3;
    const int mWarp = (w & 1) * 64;
    const int nWarp = (w >> 1) * 32;
    const int colBase = blockIdx.x * 128;
    const int rowBase = blockIdx.z * 128;
    const uint32_t sb = smem_u32(smem);

    const uint32_t aLane = A_LANE_OFF(mWarp, lane);
    const uint32_t bLane = B_LANE_OFF(nWarp, lane);

    float* sbias = (float*)(smem + Q_NSTG * Q_STAGE);
    if (tid < 128) {
        const int o = colBase + tid;
        const int h = o >> 5, f = o & 31;
        sbias[tid] = bq[(h * N_ + nJ) * F_ + f];
    }

    float c[4][4][4];
#pragma unroll
    for (int mi = 0; mi < 4; mi++)
#pragma unroll
        for (int ni = 0; ni < 4; ni++)
#pragma unroll
            for (int j = 0; j < 4; j++) c[mi][ni][j] = 0.f;

    auto load_stage = [&](int ch) {
        const int s = ch % Q_NSTG;
        const int k0 = ch * 64;
        const uint32_t aBase = sb + s * Q_STAGE;
        const uint32_t bBase = aBase + TILE_BYTES;
#pragma unroll
        for (int j = 0; j < 4; j++) {
            const int e = tid + 256 * j;
            const int r = e >> 3, cc = e & 7;
            const uint32_t soff = (uint32_t)(r * ROWB + cc * 16);
            cp_async16(aBase + soff,
                       g_xh + (size_t)(rowBase + r) * ND_ + nJ * D_ + k0 + cc * 8);
            const int o = colBase + r;
            const int h = o >> 5, f = o & 31;
            cp_async16(bBase + soff,
                       g_wqh + ((size_t)(h * N_ + nJ) * F_ + f) * D_ + k0 + cc * 8);
        }
    };

    load_stage(0); cp_commit();
    load_stage(1); cp_commit();

    for (int ch = 0; ch < 4; ch++) {
        if (ch < 3) cp_wait1(); else cp_wait0();
        __syncthreads();
        if (ch + 2 < 4) { load_stage(ch + 2); cp_commit(); }
        const uint32_t aBase = sb + (ch % Q_NSTG) * Q_STAGE;
        const uint32_t bBase = aBase + TILE_BYTES;
#pragma unroll
        for (int ks = 0; ks < 4; ks++) {
            const uint32_t kOff = (uint32_t)(ks * 32);
            uint32_t af[4][4];
#pragma unroll
            for (int mi = 0; mi < 4; mi++)
                LDMX4(af[mi][0], af[mi][1], af[mi][2], af[mi][3],
                      aBase + aLane + (uint32_t)(mi * 16 * ROWB) + kOff);
            uint32_t bf[4][2];
#pragma unroll
            for (int np = 0; np < 2; np++) {
                LDMX4(bf[2 * np][0], bf[2 * np][1], bf[2 * np + 1][0], bf[2 * np + 1][1],
                      bBase + bLane + (uint32_t)(np * 16 * ROWB) + kOff);
            }
#pragma unroll
            for (int mi = 0; mi < 4; mi++)
#pragma unroll
                for (int ni = 0; ni < 4; ni++)
                    mma_f16(c[mi][ni], af[mi], bf[ni]);
        }
    }

#pragma unroll
    for (int mi = 0; mi < 4; mi++) {
        const int r0 = rowBase + mWarp + mi * 16 + gid;
#pragma unroll
        for (int rr = 0; rr < 2; rr++) {
            const int tb = r0 + rr * 8;
#pragma unroll
            for (int ni = 0; ni < 4; ni++) {
                const int oc = nWarp + ni * 8 + tig * 2;
                const int o = colBase + oc;
                const int h = o >> 5, f = o & 31;
                __half2 v = __floats2half2_rn(c[mi][ni][2 * rr + 0] + sbias[oc],
                                              c[mi][ni][2 * rr + 1] + sbias[oc + 1]);
                *(__half2*)&g_q[(((size_t)tb * H_ + h) * N_ + nJ) * F_ + f] = v;
            }
        }
    }
}

// ---------------------------------------------------------------------------
// Kernel 3: tensor-core attention (unchanged from R11, validated).
// ---------------------------------------------------------------------------
#define AROW 20   // words per smem row (conflict-free)

__global__ __launch_bounds__(128)
void attn_kernel(float* __restrict__ out)
{
    __shared__ uint32_t sm[4][3][32 * AROW];

    const int tb   = blockIdx.x;
    const int w    = threadIdx.x >> 5;
    const int lane = threadIdx.x & 31;
    const int gid  = lane >> 2, tig = lane & 3;
    const int h    = blockIdx.y * 4 + w;

    uint32_t* qs = sm[w][0];
    uint32_t* ks = sm[w][1];
    uint32_t* vs = sm[w][2];

    const size_t base = ((size_t)(tb * H_ + h)) * N_ * F_;
    const uint2* qg = (const uint2*)(g_q + base);
    const uint2* kg = (const uint2*)(g_k + base);
    const uint2* vg = (const uint2*)(g_v + base);

    for (int i = lane; i < 24 * 8; i += 32) {
        const int r = i >> 3, cc = i & 7;
        *(uint2*)&qs[r * AROW + cc * 2] = qg[i];
        *(uint2*)&ks[r * AROW + cc * 2] = kg[i];
    }
    __half* vsh = (__half*)vs;
    for (int i = lane; i < 24 * 8; i += 32) {
        const int m = i >> 3, cc = i & 7;
        uint2 u = vg[i];
        __half2 h01 = *(__half2*)&u.x, h23 = *(__half2*)&u.y;
        const int f0 = cc * 4;
        vsh[(f0 + 0) * (2 * AROW) + m] = __low2half(h01);
        vsh[(f0 + 1) * (2 * AROW) + m] = __high2half(h01);
        vsh[(f0 + 2) * (2 * AROW) + m] = __low2half(h23);
        vsh[(f0 + 3) * (2 * AROW) + m] = __high2half(h23);
    }
    *(uint4*)&vsh[lane * (2 * AROW) + 24] = make_uint4(0, 0, 0, 0);
    __syncwarp();

    float cs[2][3][4];
#pragma unroll
    for (int mi = 0; mi < 2; mi++)
#pragma unroll
        for (int ni = 0; ni < 3; ni++)
#pragma unroll
            for (int j = 0; j < 4; j++) cs[mi][ni][j] = 0.f;

#pragma unroll
    for (int kb = 0; kb < 2; kb++) {
        uint32_t a[2][4];
#pragma unroll
        for (int mi = 0; mi < 2; mi++) {
            const int r = mi * 16 + gid;
            a[mi][0] = qs[(r)     * AROW + kb * 8 + tig];
            a[mi][1] = qs[(r + 8) * AROW + kb * 8 + tig];
            a[mi][2] = qs[(r)     * AROW + kb * 8 + tig + 4];
            a[mi][3] = qs[(r + 8) * AROW + kb * 8 + tig + 4];
        }
#pragma unroll
        for (int ni = 0; ni < 3; ni++) {
            uint32_t b[2];
            b[0] = ks[(ni * 8 + gid) * AROW + kb * 8 + tig];
            b[1] = ks[(ni * 8 + gid) * AROW + kb * 8 + tig + 4];
#pragma unroll
            for (int mi = 0; mi < 2; mi++) mma_f16(cs[mi][ni], a[mi], b);
        }
    }

    const float scale = 0.17677669529663687f;  // 1/sqrt(32)
    float p[2][3][4];
#pragma unroll
    for (int mi = 0; mi < 2; mi++) {
        float m0 = -1e30f, m1 = -1e30f;
#pragma unroll
        for (int ni = 0; ni < 3; ni++) {
            m0 = fmaxf(m0, fmaxf(cs[mi][ni][0], cs[mi][ni][1]));
            m1 = fmaxf(m1, fmaxf(cs[mi][ni][2], cs[mi][ni][3]));
        }
        m0 = fmaxf(m0, __shfl_xor_sync(0xffffffffu, m0, 1));
        m0 = fmaxf(m0, __shfl_xor_sync(0xffffffffu, m0, 2));
        m1 = fmaxf(m1, __shfl_xor_sync(0xffffffffu, m1, 1));
        m1 = fmaxf(m1, __shfl_xor_sync(0xffffffffu, m1, 2));

        float s0 = 0.f, s1 = 0.f;
#pragma unroll
        for (int ni = 0; ni < 3; ni++) {
            p[mi][ni][0] = __expf((cs[mi][ni][0] - m0) * scale);
            p[mi][ni][1] = __expf((cs[mi][ni][1] - m0) * scale);
            p[mi][ni][2] = __expf((cs[mi][ni][2] - m1) * scale);
            p[mi][ni][3] = __expf((cs[mi][ni][3] - m1) * scale);
            s0 += p[mi][ni][0] + p[mi][ni][1];
            s1 += p[mi][ni][2] + p[mi][ni][3];
        }
        s0 += __shfl_xor_sync(0xffffffffu, s0, 1);
        s0 += __shfl_xor_sync(0xffffffffu, s0, 2);
        s1 += __shfl_xor_sync(0xffffffffu, s1, 1);
        s1 += __shfl_xor_sync(0xffffffffu, s1, 2);
        const float i0 = __frcp_rn(s0), i1 = __frcp_rn(s1);
#pragma unroll
        for (int ni = 0; ni < 3; ni++) {
            p[mi][ni][0] *= i0; p[mi][ni][1] *= i0;
            p[mi][ni][2] *= i1; p[mi][ni][3] *= i1;
        }
    }

    float co[2][4][4];
#pragma unroll
    for (int mi = 0; mi < 2; mi++)
#pragma unroll
        for (int nj = 0; nj < 4; nj++)
#pragma unroll
            for (int j = 0; j < 4; j++) co[mi][nj][j] = 0.f;

#pragma unroll
    for (int mi = 0; mi < 2; mi++) {
        uint32_t ap0[4], ap1[4];
        ap0[0] = packh2(p[mi][0][0], p[mi][0][1]);
        ap0[1] = packh2(p[mi][0][2], p[mi][0][3]);
        ap0[2] = packh2(p[mi][1][0], p[mi][1][1]);
        ap0[3] = packh2(p[mi][1][2], p[mi][1][3]);
        ap1[0] = packh2(p[mi][2][0], p[mi][2][1]);
        ap1[1] = packh2(p[mi][2][2], p[mi][2][3]);
        ap1[2] = 0u; ap1[3] = 0u;
#pragma unroll
        for (int nj = 0; nj < 4; nj++) {
            uint32_t b0[2], b1[2];
            b0[0] = vs[(nj * 8 + gid) * AROW + tig];
            b0[1] = vs[(nj * 8 + gid) * AROW + tig + 4];
            b1[0] = vs[(nj * 8 + gid) * AROW + 8 + tig];
            b1[1] = vs[(nj * 8 + gid) * AROW + 8 + tig + 4];
            mma_f16(co[mi][nj], ap0, b0);
            mma_f16(co[mi][nj], ap1, b1);
        }
    }

#pragma unroll
    for (int mi = 0; mi < 2; mi++) {
        const int r0 = mi * 16 + gid;
#pragma unroll
        for (int nj = 0; nj < 4; nj++) {
            const int fcol = nj * 8 + 2 * tig;
            float2 v0;
            v0.x = co[mi][nj][0]; v0.y = co[mi][nj][1];
            *(float2*)&out[(size_t)tb * OUTW_ + (r0 * H_ + h) * F_ + fcol] = v0;
            if (mi == 0) {
                float2 v1;
                v1.x = co[mi][nj][2]; v1.y = co[mi][nj][3];
                *(float2*)&out[(size_t)tb * OUTW_ + ((r0 + 8) * H_ + h) * F_ + fcol] = v1;
            }
        }
    }
}

// ---------------------------------------------------------------------------
extern "C" void kernel_launch(void* const* d_in, const int* in_sizes, int n_in,
                              void* d_out, int out_size)
{
    const float* x  = (const float*)d_in[0];
    const float* Wk = (const float*)d_in[1];
    const float* bk = (const float*)d_in[2];
    const float* Wv = (const float*)d_in[3];
    const float* bv = (const float*)d_in[4];
    const float* Wq = (const float*)d_in[5];
    const float* bq = (const float*)d_in[6];
    float* out = (float*)d_out;

    cudaFuncSetAttribute(kv_mma_kernel,
                         cudaFuncAttributeMaxDynamicSharedMemorySize, KV_SMEM);
    cudaFuncSetAttribute(q_mma_kernel,
                         cudaFuncAttributeMaxDynamicSharedMemorySize, Q_SMEM);

    void* xh; void* wkh; void* wvh; void* wqh;
    cudaGetSymbolAddress(&xh,  g_xh);
    cudaGetSymbolAddress(&wkh, g_wkh);
    cudaGetSymbolAddress(&wvh, g_wvh);
    cudaGetSymbolAddress(&wqh, g_wqh);

    // Pre-pass: fp32 -> fp16 once.
    conv_h_kernel<<<8192, 256>>>((const float4*)x,  (uint2*)xh,  TB_ * ND_ / 4);
    conv_h_kernel<<<64,   256>>>((const float4*)Wk, (uint2*)wkh, HF_ * D_ / 4);
    conv_h_kernel<<<64,   256>>>((const float4*)Wv, (uint2*)wvh, HF_ * D_ / 4);
    conv_h_kernel<<<1536, 256>>>((const float4*)Wq, (uint2*)wqh, H_ * N_ * F_ * D_ / 4);

    dim3 g1(2, M1_ / 128);
    kv_mma_kernel<<<g1, 256, KV_SMEM>>>(bk, bv);

    dim3 g2(2, N_, TB_ / 128);
    q_mma_kernel<<<g2, 256, Q_SMEM>>>(bq);

    dim3 g3(TB_, 2);
    attn_kernel<<<g3, 128>>>(out);
}